// round 3
// baseline (speedup 1.0000x reference)
#include <cuda_runtime.h>
#include <math_constants.h>

#define NQ      4
#define LPATCH  (14*14)
#define BATCH   128
#define LTOT    (BATCH*LPATCH)   // 25088
#define NFEAT   784

__device__ float g_feat[BATCH * NFEAT];

// ---- single-qubit gate helpers (m = bit mask of qubit, compile-time after unroll) ----

// Ry: [[c,-s],[s,c]] (real)
__device__ __forceinline__ void apply_ry(float2* a, int m, float c, float s) {
#pragma unroll
    for (int i = 0; i < 16; i++) {
        if (!(i & m)) {
            float2 a0 = a[i], a1 = a[i | m];
            a[i].x     = c * a0.x - s * a1.x;
            a[i].y     = c * a0.y - s * a1.y;
            a[i | m].x = s * a0.x + c * a1.x;
            a[i | m].y = s * a0.y + c * a1.y;
        }
    }
}

// Rz: diag(e^{-i t/2}, e^{+i t/2}); c=cos(t/2), s=sin(t/2)
__device__ __forceinline__ void apply_rz(float2* a, int m, float c, float s) {
#pragma unroll
    for (int i = 0; i < 16; i++) {
        float2 v = a[i];
        if (i & m) {   // * (c + i s)
            a[i].x = v.x * c - v.y * s;
            a[i].y = v.y * c + v.x * s;
        } else {       // * (c - i s)
            a[i].x = v.x * c + v.y * s;
            a[i].y = v.y * c - v.x * s;
        }
    }
}

// CNOT(control mask mc, target mask mt): pure permutation
__device__ __forceinline__ void apply_cnot(float2* a, int mc, int mt) {
#pragma unroll
    for (int i = 0; i < 16; i++) {
        if ((i & mc) && !(i & mt)) {
            float2 tmp = a[i];
            a[i] = a[i | mt];
            a[i | mt] = tmp;
        }
    }
}

__global__ void __launch_bounds__(256) circuit_kernel(
    const float* __restrict__ x,      // [128,1,28,28]
    const float* __restrict__ w,      // [60]
    float* __restrict__ feat)         // [128,784]
{
    __shared__ float wc[60], ws[60];
    int t = threadIdx.x;
    if (t < 60) {
        float s, c;
        sincosf(0.5f * w[t], &s, &c);
        ws[t] = s; wc[t] = c;
    }
    __syncthreads();

    int tid = blockIdx.x * blockDim.x + t;
    if (tid >= LTOT) return;

    int b = tid / LPATCH;
    int p = tid - b * LPATCH;
    int pi = p / 14, pj = p - pi * 14;

    const float* xb = x + b * 784;
    float xv[4];
    xv[0] = xb[(2 * pi) * 28 + 2 * pj];
    xv[1] = xb[(2 * pi) * 28 + 2 * pj + 1];
    xv[2] = xb[(2 * pi + 1) * 28 + 2 * pj];
    xv[3] = xb[(2 * pi + 1) * 28 + 2 * pj + 1];

    // Rx encoding angle = 2*pi*x; half-angle = pi*x
    float hc[4], hs[4];
#pragma unroll
    for (int q = 0; q < 4; q++)
        sincosf(CUDART_PI_F * xv[q], &hs[q], &hc[q]);

    // Initial state = tensor product of Rx columns applied to |0>:
    // amp(bits) = prod_q (bit? sin : cos) * (-i)^popcount(bits)
    float2 amp[16];
#pragma unroll
    for (int s2 = 0; s2 < 16; s2++) {
        float r = (s2 & 8 ? hs[0] : hc[0]) *
                  (s2 & 4 ? hs[1] : hc[1]) *
                  (s2 & 2 ? hs[2] : hc[2]) *
                  (s2 & 1 ? hs[3] : hc[3]);
        int k = ((s2 >> 3) & 1) + ((s2 >> 2) & 1) + ((s2 >> 1) & 1) + (s2 & 1);
        // (-i)^k: 0->(1,0) 1->(0,-1) 2->(-1,0) 3->(0,1)
        switch (k & 3) {
            case 0: amp[s2].x =  r;   amp[s2].y = 0.f;  break;
            case 1: amp[s2].x =  0.f; amp[s2].y = -r;   break;
            case 2: amp[s2].x = -r;   amp[s2].y = 0.f;  break;
            default:amp[s2].x =  0.f; amp[s2].y =  r;   break;
        }
    }

    // 5 variational layers
#pragma unroll
    for (int l = 0; l < 5; l++) {
        const int base = l * 12;
#pragma unroll
        for (int q = 0; q < 4; q++) apply_ry(amp, 8 >> q, wc[base + q],     ws[base + q]);
#pragma unroll
        for (int q = 0; q < 4; q++) apply_rz(amp, 8 >> q, wc[base + 4 + q], ws[base + 4 + q]);
#pragma unroll
        for (int q = 0; q < 4; q++) apply_ry(amp, 8 >> q, wc[base + 8 + q], ws[base + 8 + q]);
        if (l < 4) {
            apply_cnot(amp, 8, 4);
            apply_cnot(amp, 4, 2);
            apply_cnot(amp, 2, 1);
            apply_cnot(amp, 1, 8);
        }
    }

    // <Z_q> expectations
    float e0 = 0.f, e1 = 0.f, e2 = 0.f, e3 = 0.f;
#pragma unroll
    for (int s2 = 0; s2 < 16; s2++) {
        float pp = amp[s2].x * amp[s2].x + amp[s2].y * amp[s2].y;
        e0 += (s2 & 8) ? -pp : pp;
        e1 += (s2 & 4) ? -pp : pp;
        e2 += (s2 & 2) ? -pp : pp;
        e3 += (s2 & 1) ? -pp : pp;
    }

    float* f = feat + b * NFEAT + p * 4;
    f[0] = e0; f[1] = e1; f[2] = e2; f[3] = e3;
}

__global__ void __launch_bounds__(64) mlp_kernel(
    const float* __restrict__ feat,   // [128,784]
    const float* __restrict__ w1,     // [64,784]
    const float* __restrict__ b1,     // [64]
    const float* __restrict__ w2,     // [10,64]
    const float* __restrict__ b2,     // [10]
    float* __restrict__ out)          // [128,10]
{
    __shared__ float sf[NFEAT];
    __shared__ float sh[64];
    int b = blockIdx.x, t = threadIdx.x;

    for (int k = t; k < NFEAT; k += 64)
        sf[k] = feat[b * NFEAT + k];
    __syncthreads();

    // h = relu(feat @ w1^T + b1)
    const float4* wr = reinterpret_cast<const float4*>(w1 + t * NFEAT);
    const float4* sfv = reinterpret_cast<const float4*>(sf);
    float acc = b1[t];
#pragma unroll 4
    for (int k = 0; k < NFEAT / 4; k++) {
        float4 wv = wr[k];
        float4 fv = sfv[k];
        acc = fmaf(fv.x, wv.x, acc);
        acc = fmaf(fv.y, wv.y, acc);
        acc = fmaf(fv.z, wv.z, acc);
        acc = fmaf(fv.w, wv.w, acc);
    }
    sh[t] = fmaxf(acc, 0.f);
    __syncthreads();

    if (t < 10) {
        float o = b2[t];
        const float* w2r = w2 + t * 64;
#pragma unroll
        for (int k = 0; k < 64; k++)
            o = fmaf(sh[k], w2r[k], o);
        out[b * 10 + t] = o;
    }
}

extern "C" void kernel_launch(void* const* d_in, const int* in_sizes, int n_in,
                              void* d_out, int out_size) {
    const float* x     = (const float*)d_in[0];
    const float* w     = (const float*)d_in[1];
    const float* fc1_w = (const float*)d_in[2];
    const float* fc1_b = (const float*)d_in[3];
    const float* fc2_w = (const float*)d_in[4];
    const float* fc2_b = (const float*)d_in[5];
    float* out = (float*)d_out;

    circuit_kernel<<<(LTOT + 255) / 256, 256>>>(x, w, g_feat);
    mlp_kernel<<<BATCH, 64>>>(g_feat, fc1_w, fc1_b, fc2_w, fc2_b, out);
}

// round 4
// speedup vs baseline: 1.1439x; 1.1439x over previous
#include <cuda_runtime.h>
#include <math_constants.h>

#define NQ      4
#define LPATCH  (14*14)
#define BATCH   128
#define LTOT    (BATCH*LPATCH)   // 25088
#define NFEAT   784
#define NHID    64

__device__ float g_feat[BATCH * NFEAT];
__device__ float g_hid[BATCH * NHID];

// ---- single-qubit gate helpers (m = bit mask of qubit, compile-time after unroll) ----

__device__ __forceinline__ void apply_ry(float2* a, int m, float c, float s) {
#pragma unroll
    for (int i = 0; i < 16; i++) {
        if (!(i & m)) {
            float2 a0 = a[i], a1 = a[i | m];
            a[i].x     = c * a0.x - s * a1.x;
            a[i].y     = c * a0.y - s * a1.y;
            a[i | m].x = s * a0.x + c * a1.x;
            a[i | m].y = s * a0.y + c * a1.y;
        }
    }
}

__device__ __forceinline__ void apply_rz(float2* a, int m, float c, float s) {
#pragma unroll
    for (int i = 0; i < 16; i++) {
        float2 v = a[i];
        if (i & m) {
            a[i].x = v.x * c - v.y * s;
            a[i].y = v.y * c + v.x * s;
        } else {
            a[i].x = v.x * c + v.y * s;
            a[i].y = v.y * c - v.x * s;
        }
    }
}

__device__ __forceinline__ void apply_cnot(float2* a, int mc, int mt) {
#pragma unroll
    for (int i = 0; i < 16; i++) {
        if ((i & mc) && !(i & mt)) {
            float2 tmp = a[i];
            a[i] = a[i | mt];
            a[i | mt] = tmp;
        }
    }
}

__global__ void __launch_bounds__(256) circuit_kernel(
    const float* __restrict__ x,      // [128,1,28,28]
    const float* __restrict__ w,      // [60]
    float* __restrict__ feat)         // [128,784]
{
    __shared__ float wc[60], ws[60];
    int t = threadIdx.x;
    if (t < 60) {
        float s, c;
        sincosf(0.5f * w[t], &s, &c);
        ws[t] = s; wc[t] = c;
    }
    __syncthreads();

    int tid = blockIdx.x * blockDim.x + t;
    if (tid >= LTOT) return;

    int b = tid / LPATCH;
    int p = tid - b * LPATCH;
    int pi = p / 14, pj = p - pi * 14;

    const float* xb = x + b * 784;
    float xv[4];
    xv[0] = xb[(2 * pi) * 28 + 2 * pj];
    xv[1] = xb[(2 * pi) * 28 + 2 * pj + 1];
    xv[2] = xb[(2 * pi + 1) * 28 + 2 * pj];
    xv[3] = xb[(2 * pi + 1) * 28 + 2 * pj + 1];

    float hc[4], hs[4];
#pragma unroll
    for (int q = 0; q < 4; q++)
        sincosf(CUDART_PI_F * xv[q], &hs[q], &hc[q]);

    // amp(bits) = prod_q (bit? sin : cos) * (-i)^popcount(bits)
    float2 amp[16];
#pragma unroll
    for (int s2 = 0; s2 < 16; s2++) {
        float r = (s2 & 8 ? hs[0] : hc[0]) *
                  (s2 & 4 ? hs[1] : hc[1]) *
                  (s2 & 2 ? hs[2] : hc[2]) *
                  (s2 & 1 ? hs[3] : hc[3]);
        int k = ((s2 >> 3) & 1) + ((s2 >> 2) & 1) + ((s2 >> 1) & 1) + (s2 & 1);
        switch (k & 3) {
            case 0: amp[s2].x =  r;   amp[s2].y = 0.f;  break;
            case 1: amp[s2].x =  0.f; amp[s2].y = -r;   break;
            case 2: amp[s2].x = -r;   amp[s2].y = 0.f;  break;
            default:amp[s2].x =  0.f; amp[s2].y =  r;   break;
        }
    }

#pragma unroll
    for (int l = 0; l < 5; l++) {
        const int base = l * 12;
#pragma unroll
        for (int q = 0; q < 4; q++) apply_ry(amp, 8 >> q, wc[base + q],     ws[base + q]);
#pragma unroll
        for (int q = 0; q < 4; q++) apply_rz(amp, 8 >> q, wc[base + 4 + q], ws[base + 4 + q]);
#pragma unroll
        for (int q = 0; q < 4; q++) apply_ry(amp, 8 >> q, wc[base + 8 + q], ws[base + 8 + q]);
        if (l < 4) {
            apply_cnot(amp, 8, 4);
            apply_cnot(amp, 4, 2);
            apply_cnot(amp, 2, 1);
            apply_cnot(amp, 1, 8);
        }
    }

    float e0 = 0.f, e1 = 0.f, e2 = 0.f, e3 = 0.f;
#pragma unroll
    for (int s2 = 0; s2 < 16; s2++) {
        float pp = amp[s2].x * amp[s2].x + amp[s2].y * amp[s2].y;
        e0 += (s2 & 8) ? -pp : pp;
        e1 += (s2 & 4) ? -pp : pp;
        e2 += (s2 & 2) ? -pp : pp;
        e3 += (s2 & 1) ? -pp : pp;
    }

    float* f = feat + b * NFEAT + p * 4;
    f[0] = e0; f[1] = e1; f[2] = e2; f[3] = e3;
}

// Layer 1: one warp per (batch row, hidden neuron). 8192 warps total.
__global__ void __launch_bounds__(256) mlp1_kernel(
    const float* __restrict__ feat,   // [128,784]
    const float* __restrict__ w1,     // [64,784]
    const float* __restrict__ b1,     // [64]
    float* __restrict__ hid)          // [128,64]
{
    int gtid = blockIdx.x * blockDim.x + threadIdx.x;
    int warp = gtid >> 5;
    int lane = gtid & 31;
    if (warp >= BATCH * NHID) return;
    int b = warp >> 6;
    int n = warp & 63;

    const float4* fv = reinterpret_cast<const float4*>(feat + b * NFEAT);
    const float4* wv = reinterpret_cast<const float4*>(w1 + n * NFEAT);

    float acc = 0.f;
    // 196 float4 per row: lanes 0-3 do 7 iters, lanes 4-31 do 6
#pragma unroll
    for (int k = lane; k < NFEAT / 4; k += 32) {
        float4 a = fv[k];
        float4 ww = wv[k];
        acc = fmaf(a.x, ww.x, acc);
        acc = fmaf(a.y, ww.y, acc);
        acc = fmaf(a.z, ww.z, acc);
        acc = fmaf(a.w, ww.w, acc);
    }
#pragma unroll
    for (int off = 16; off > 0; off >>= 1)
        acc += __shfl_xor_sync(0xffffffffu, acc, off);

    if (lane == 0)
        hid[b * NHID + n] = fmaxf(acc + b1[n], 0.f);
}

// Layer 2: one warp per (batch row, output). 1280 warps total.
__global__ void __launch_bounds__(256) mlp2_kernel(
    const float* __restrict__ hid,    // [128,64]
    const float* __restrict__ w2,     // [10,64]
    const float* __restrict__ b2,     // [10]
    float* __restrict__ out)          // [128,10]
{
    int gtid = blockIdx.x * blockDim.x + threadIdx.x;
    int warp = gtid >> 5;
    int lane = gtid & 31;
    if (warp >= BATCH * 10) return;
    int b = warp / 10;
    int o = warp - b * 10;

    float acc = 0.f;
    if (lane < 16) {
        const float4* hv = reinterpret_cast<const float4*>(hid + b * NHID);
        const float4* wv = reinterpret_cast<const float4*>(w2 + o * NHID);
        float4 h = hv[lane];
        float4 ww = wv[lane];
        acc = h.x * ww.x + h.y * ww.y + h.z * ww.z + h.w * ww.w;
    }
#pragma unroll
    for (int off = 8; off > 0; off >>= 1)
        acc += __shfl_xor_sync(0xffffffffu, acc, off);

    if (lane == 0)
        out[b * 10 + o] = acc + b2[o];
}

extern "C" void kernel_launch(void* const* d_in, const int* in_sizes, int n_in,
                              void* d_out, int out_size) {
    const float* x     = (const float*)d_in[0];
    const float* w     = (const float*)d_in[1];
    const float* fc1_w = (const float*)d_in[2];
    const float* fc1_b = (const float*)d_in[3];
    const float* fc2_w = (const float*)d_in[4];
    const float* fc2_b = (const float*)d_in[5];
    float* out = (float*)d_out;

    circuit_kernel<<<(LTOT + 255) / 256, 256>>>(x, w, g_feat);
    // 8192 warps -> 1024 blocks of 256 threads
    mlp1_kernel<<<(BATCH * NHID * 32 + 255) / 256, 256>>>(g_feat, fc1_w, fc1_b, g_hid);
    // 1280 warps -> 160 blocks of 256 threads
    mlp2_kernel<<<(BATCH * 10 * 32 + 255) / 256, 256>>>(g_hid, fc2_w, fc2_b, out);
}

// round 5
// speedup vs baseline: 1.9547x; 1.7088x over previous
#include <cuda_runtime.h>
#include <math_constants.h>

#define NQ      4
#define LPATCH  (14*14)
#define BATCH   128
#define LTOT    (BATCH*LPATCH)   // 25088
#define NFEAT   784
#define NHID    64

__device__ float g_feat[BATCH * NFEAT];
__device__ float g_hid[BATCH * NHID];

// Fused SU(2) gate U = Ry(c)Rz(b)Ry(a) packed as float4:
//   u.x = cB*cosP, u.y = sB*cosQ, u.z = cB*sinP, u.w = sB*sinQ
//   (P=(a+c)/2, Q=(a-c)/2, B=b/2)
//   u00 = (u.x, -u.y)  u01 = (-u.z, u.w)
//   u10 = (u.z,  u.w)  u11 = ( u.x, u.y)
__device__ __forceinline__ void apply_u(float2* a, int m, float4 u) {
#pragma unroll
    for (int i = 0; i < 16; i++) {
        if (!(i & m)) {
            float2 a0 = a[i], a1 = a[i | m];
            float r0 = u.x * a0.x + u.y * a0.y - u.z * a1.x - u.w * a1.y;
            float i0 = u.x * a0.y - u.y * a0.x - u.z * a1.y + u.w * a1.x;
            float r1 = u.z * a0.x - u.w * a0.y + u.x * a1.x - u.y * a1.y;
            float i1 = u.z * a0.y + u.w * a0.x + u.x * a1.y + u.y * a1.x;
            a[i].x = r0;     a[i].y = i0;
            a[i | m].x = r1; a[i | m].y = i1;
        }
    }
}

__device__ __forceinline__ void apply_cnot(float2* a, int mc, int mt) {
#pragma unroll
    for (int i = 0; i < 16; i++) {
        if ((i & mc) && !(i & mt)) {
            float2 tmp = a[i];
            a[i] = a[i | mt];
            a[i | mt] = tmp;
        }
    }
}

__global__ void __launch_bounds__(64) circuit_kernel(
    const float* __restrict__ x,      // [128,1,28,28]
    const float* __restrict__ w,      // [60]
    float* __restrict__ feat)         // [128,784]
{
    __shared__ float4 um[16];         // fused U for layers 0..3, qubits 0..3
    __shared__ float  meas[4][3];     // nz,nx,ny per qubit (layer 4 folded into measurement)

    int t = threadIdx.x;
    if (t < 16) {
        int l = t >> 2, q = t & 3;
        float a = w[l * 12 + q], b = w[l * 12 + 4 + q], c = w[l * 12 + 8 + q];
        float sP, cP, sQ, cQ, sB, cB;
        sincosf(0.5f * (a + c), &sP, &cP);
        sincosf(0.5f * (a - c), &sQ, &cQ);
        sincosf(0.5f * b,       &sB, &cB);
        um[t] = make_float4(cB * cP, sB * cQ, cB * sP, sB * sQ);
    } else if (t < 20) {
        int q = t - 16;
        float a = w[48 + q], b = w[48 + 4 + q], c = w[48 + 8 + q];
        float sa, ca, sb, cb, sc, cc;
        sincosf(a, &sa, &ca);
        sincosf(b, &sb, &cb);
        sincosf(c, &sc, &cc);
        meas[q][0] =  cc * ca - sc * cb * sa;   // nz
        meas[q][1] = -cc * sa - sc * cb * ca;   // nx
        meas[q][2] =  sc * sb;                  // ny
    }
    __syncthreads();

    int tid = blockIdx.x * blockDim.x + t;
    if (tid >= LTOT) return;

    int b = tid / LPATCH;
    int p = tid - b * LPATCH;
    int pi = p / 14, pj = p - pi * 14;

    const float* xb = x + b * 784;
    float xv[4];
    xv[0] = xb[(2 * pi) * 28 + 2 * pj];
    xv[1] = xb[(2 * pi) * 28 + 2 * pj + 1];
    xv[2] = xb[(2 * pi + 1) * 28 + 2 * pj];
    xv[3] = xb[(2 * pi + 1) * 28 + 2 * pj + 1];

    float hc[4], hs[4];
#pragma unroll
    for (int q = 0; q < 4; q++)
        sincosf(CUDART_PI_F * xv[q], &hs[q], &hc[q]);

    // Initial state = Rx encoding applied to |0000>:
    // amp(bits) = prod_q (bit? sin : cos) * (-i)^popcount(bits)
    float2 amp[16];
#pragma unroll
    for (int s2 = 0; s2 < 16; s2++) {
        float r = (s2 & 8 ? hs[0] : hc[0]) *
                  (s2 & 4 ? hs[1] : hc[1]) *
                  (s2 & 2 ? hs[2] : hc[2]) *
                  (s2 & 1 ? hs[3] : hc[3]);
        int k = ((s2 >> 3) & 1) + ((s2 >> 2) & 1) + ((s2 >> 1) & 1) + (s2 & 1);
        switch (k & 3) {
            case 0: amp[s2].x =  r;   amp[s2].y = 0.f;  break;
            case 1: amp[s2].x =  0.f; amp[s2].y = -r;   break;
            case 2: amp[s2].x = -r;   amp[s2].y = 0.f;  break;
            default:amp[s2].x =  0.f; amp[s2].y =  r;   break;
        }
    }

    // Layers 0..3: fused yzy per qubit + CNOT ring
#pragma unroll
    for (int l = 0; l < 4; l++) {
#pragma unroll
        for (int q = 0; q < 4; q++)
            apply_u(amp, 8 >> q, um[l * 4 + q]);
        apply_cnot(amp, 8, 4);
        apply_cnot(amp, 4, 2);
        apply_cnot(amp, 2, 1);
        apply_cnot(amp, 1, 8);
    }

    // Layer 4 folded into measurement: <Z_q> = nz*<Z> + nx*<X> + ny*<Y>
    float e[4];
#pragma unroll
    for (int q = 0; q < 4; q++) {
        int m = 8 >> q;
        float z = 0.f, xx = 0.f, yy = 0.f;
#pragma unroll
        for (int i = 0; i < 16; i++) {
            if (!(i & m)) {
                float2 a0 = amp[i], a1 = amp[i | m];
                z  += a0.x * a0.x + a0.y * a0.y - a1.x * a1.x - a1.y * a1.y;
                xx += a0.x * a1.x + a0.y * a1.y;
                yy += a0.x * a1.y - a0.y * a1.x;
            }
        }
        e[q] = meas[q][0] * z + meas[q][1] * (2.f * xx) + meas[q][2] * (2.f * yy);
    }

    float* f = feat + b * NFEAT + p * 4;
    f[0] = e[0]; f[1] = e[1]; f[2] = e[2]; f[3] = e[3];
}

// Layer 1: one warp per (batch row, 4 hidden neurons). 2048 warps.
#define NPW 4
__global__ void __launch_bounds__(256) mlp1_kernel(
    const float* __restrict__ feat,   // [128,784]
    const float* __restrict__ w1,     // [64,784]
    const float* __restrict__ b1,     // [64]
    float* __restrict__ hid)          // [128,64]
{
    int gtid = blockIdx.x * blockDim.x + threadIdx.x;
    int warp = gtid >> 5;
    int lane = gtid & 31;
    if (warp >= BATCH * (NHID / NPW)) return;
    int b = warp / (NHID / NPW);
    int n0 = (warp % (NHID / NPW)) * NPW;

    const float4* fv = reinterpret_cast<const float4*>(feat + b * NFEAT);
    const float4* wv0 = reinterpret_cast<const float4*>(w1 + (n0 + 0) * NFEAT);
    const float4* wv1 = reinterpret_cast<const float4*>(w1 + (n0 + 1) * NFEAT);
    const float4* wv2 = reinterpret_cast<const float4*>(w1 + (n0 + 2) * NFEAT);
    const float4* wv3 = reinterpret_cast<const float4*>(w1 + (n0 + 3) * NFEAT);

    float acc0 = 0.f, acc1 = 0.f, acc2 = 0.f, acc3 = 0.f;
#pragma unroll
    for (int k = lane; k < NFEAT / 4; k += 32) {
        float4 a = fv[k];
        float4 w0 = wv0[k], w1v = wv1[k], w2v = wv2[k], w3v = wv3[k];
        acc0 = fmaf(a.x, w0.x, fmaf(a.y, w0.y, fmaf(a.z, w0.z, fmaf(a.w, w0.w, acc0))));
        acc1 = fmaf(a.x, w1v.x, fmaf(a.y, w1v.y, fmaf(a.z, w1v.z, fmaf(a.w, w1v.w, acc1))));
        acc2 = fmaf(a.x, w2v.x, fmaf(a.y, w2v.y, fmaf(a.z, w2v.z, fmaf(a.w, w2v.w, acc2))));
        acc3 = fmaf(a.x, w3v.x, fmaf(a.y, w3v.y, fmaf(a.z, w3v.z, fmaf(a.w, w3v.w, acc3))));
    }
#pragma unroll
    for (int off = 16; off > 0; off >>= 1) {
        acc0 += __shfl_xor_sync(0xffffffffu, acc0, off);
        acc1 += __shfl_xor_sync(0xffffffffu, acc1, off);
        acc2 += __shfl_xor_sync(0xffffffffu, acc2, off);
        acc3 += __shfl_xor_sync(0xffffffffu, acc3, off);
    }
    if (lane == 0) {
        float* h = hid + b * NHID + n0;
        h[0] = fmaxf(acc0 + b1[n0 + 0], 0.f);
        h[1] = fmaxf(acc1 + b1[n0 + 1], 0.f);
        h[2] = fmaxf(acc2 + b1[n0 + 2], 0.f);
        h[3] = fmaxf(acc3 + b1[n0 + 3], 0.f);
    }
}

// Layer 2: one warp per (batch row, output). 1280 warps.
__global__ void __launch_bounds__(256) mlp2_kernel(
    const float* __restrict__ hid,    // [128,64]
    const float* __restrict__ w2,     // [10,64]
    const float* __restrict__ b2,     // [10]
    float* __restrict__ out)          // [128,10]
{
    int gtid = blockIdx.x * blockDim.x + threadIdx.x;
    int warp = gtid >> 5;
    int lane = gtid & 31;
    if (warp >= BATCH * 10) return;
    int b = warp / 10;
    int o = warp - b * 10;

    float acc = 0.f;
    if (lane < 16) {
        const float4* hv = reinterpret_cast<const float4*>(hid + b * NHID);
        const float4* wv = reinterpret_cast<const float4*>(w2 + o * NHID);
        float4 h = hv[lane];
        float4 ww = wv[lane];
        acc = h.x * ww.x + h.y * ww.y + h.z * ww.z + h.w * ww.w;
    }
#pragma unroll
    for (int off = 8; off > 0; off >>= 1)
        acc += __shfl_xor_sync(0xffffffffu, acc, off);

    if (lane == 0)
        out[b * 10 + o] = acc + b2[o];
}

extern "C" void kernel_launch(void* const* d_in, const int* in_sizes, int n_in,
                              void* d_out, int out_size) {
    const float* x     = (const float*)d_in[0];
    const float* w     = (const float*)d_in[1];
    const float* fc1_w = (const float*)d_in[2];
    const float* fc1_b = (const float*)d_in[3];
    const float* fc2_w = (const float*)d_in[4];
    const float* fc2_b = (const float*)d_in[5];
    float* out = (float*)d_out;

    circuit_kernel<<<(LTOT + 63) / 64, 64>>>(x, w, g_feat);
    mlp1_kernel<<<(BATCH * (NHID / NPW) * 32 + 255) / 256, 256>>>(g_feat, fc1_w, fc1_b, g_hid);
    mlp2_kernel<<<(BATCH * 10 * 32 + 255) / 256, 256>>>(g_hid, fc2_w, fc2_b, out);
}